// round 1
// baseline (speedup 1.0000x reference)
#include <cuda_runtime.h>

// GIN: h = GINConv(x) -> GINConv(h) -> relu(Wf1) -> Wf2
// N=100000, E=1600000, D_IN=128, D_H=256, D_OUT=64

static constexpr int NN = 100000;
static constexpr int DHMAX = 256;

// Scratch ping-pong buffers (no cudaMalloc allowed)
__device__ __align__(128) float g_bufA[(size_t)NN * DHMAX];
__device__ __align__(128) float g_bufB[(size_t)NN * DHMAX];
__device__ __align__(128) float g_bufC[(size_t)NN * DHMAX];

// ---------------------------------------------------------------------------
// h[i] = (1 + eps) * x[i]   (seed the accumulator before edge scatter-adds)
// ---------------------------------------------------------------------------
__global__ void scale_init_kernel(float* __restrict__ h, const float* __restrict__ x,
                                  const float* __restrict__ eps, int n4) {
    float s = 1.0f + eps[0];
    const float4* x4 = (const float4*)x;
    float4* h4 = (float4*)h;
    for (int i = blockIdx.x * blockDim.x + threadIdx.x; i < n4;
         i += gridDim.x * blockDim.x) {
        float4 v = x4[i];
        h4[i] = make_float4(s * v.x, s * v.y, s * v.z, s * v.w);
    }
}

// Vectorized no-return global reduction (REDG) — sm_90+
__device__ __forceinline__ void red_add_v4(float* p, float a, float b, float c, float d) {
    asm volatile("red.global.add.v4.f32 [%0], {%1,%2,%3,%4};"
                 :: "l"(p), "f"(a), "f"(b), "f"(c), "f"(d)
                 : "memory");
}

// ---------------------------------------------------------------------------
// SpMM scatter: h[row[e]] += vals[e] * x[col[e]]   (one warp per edge)
// ---------------------------------------------------------------------------
template<int D>
__global__ void spmm_kernel(const int* __restrict__ row, const int* __restrict__ col,
                            const float* __restrict__ vals, const float* __restrict__ x,
                            float* __restrict__ h, int E) {
    int warp = (blockIdx.x * blockDim.x + threadIdx.x) >> 5;
    int lane = threadIdx.x & 31;
    if (warp >= E) return;
    int r = __ldg(row + warp);
    int c = __ldg(col + warp);
    float v = __ldg(vals + warp);
    const float4* xs = (const float4*)(x + (size_t)c * D);
    float* hd = h + (size_t)r * D;
#pragma unroll
    for (int i = 0; i < D / 128; i++) {
        int j = lane + i * 32;
        float4 xv = __ldg(xs + j);
        red_add_v4(hd + 4 * j, v * xv.x, v * xv.y, v * xv.z, v * xv.w);
    }
}

// ---------------------------------------------------------------------------
// C[n, Fout] = A[n, K] @ W[Fout, K]^T + bias  (optional ReLU)
// 128x{128,64} tile, BK=16, 8x8 register micro-tile
// ---------------------------------------------------------------------------
template<int BN, bool RELU>
__global__ __launch_bounds__((BN / 8) * 16)
void gemm_bias_kernel(const float* __restrict__ A, const float* __restrict__ W,
                      const float* __restrict__ bias, float* __restrict__ C,
                      int n, int K, int Fout) {
    constexpr int BM = 128, BK = 16, TM = 8, TN = 8;
    constexpr int TX = BN / TN;      // threads along N
    constexpr int TY = BM / TM;      // 16 threads along M
    constexpr int NT = TX * TY;

    __shared__ float As[BK][BM];
    __shared__ float Bs[BK][BN];

    const int tid = threadIdx.x;
    const int tx = tid % TX;
    const int ty = tid / TX;
    const int rowBase = blockIdx.x * BM;
    const int colBase = blockIdx.y * BN;

    float acc[TM][TN];
#pragma unroll
    for (int i = 0; i < TM; i++)
#pragma unroll
        for (int j = 0; j < TN; j++) acc[i][j] = 0.0f;

    constexpr int AL = (BM * BK / 4) / NT;  // float4 loads/thread for A tile
    constexpr int BL = (BN * BK / 4) / NT;  // float4 loads/thread for B tile

    for (int k0 = 0; k0 < K; k0 += BK) {
#pragma unroll
        for (int l = 0; l < AL; l++) {
            int idx = tid + l * NT;
            int ar = idx / (BK / 4);
            int ak = (idx % (BK / 4)) * 4;
            float4 v = make_float4(0.f, 0.f, 0.f, 0.f);
            int gr = rowBase + ar;
            if (gr < n) v = *(const float4*)(A + (size_t)gr * K + k0 + ak);
            As[ak + 0][ar] = v.x; As[ak + 1][ar] = v.y;
            As[ak + 2][ar] = v.z; As[ak + 3][ar] = v.w;
        }
#pragma unroll
        for (int l = 0; l < BL; l++) {
            int idx = tid + l * NT;
            int br = idx / (BK / 4);
            int bk = (idx % (BK / 4)) * 4;
            float4 v = *(const float4*)(W + (size_t)(colBase + br) * K + k0 + bk);
            Bs[bk + 0][br] = v.x; Bs[bk + 1][br] = v.y;
            Bs[bk + 2][br] = v.z; Bs[bk + 3][br] = v.w;
        }
        __syncthreads();
#pragma unroll
        for (int kk = 0; kk < BK; kk++) {
            float ra[TM], rb[TN];
#pragma unroll
            for (int i = 0; i < TM; i++) ra[i] = As[kk][ty * TM + i];
#pragma unroll
            for (int j = 0; j < TN; j++) rb[j] = Bs[kk][tx * TN + j];
#pragma unroll
            for (int i = 0; i < TM; i++)
#pragma unroll
                for (int j = 0; j < TN; j++)
                    acc[i][j] = fmaf(ra[i], rb[j], acc[i][j]);
        }
        __syncthreads();
    }

#pragma unroll
    for (int i = 0; i < TM; i++) {
        int gr = rowBase + ty * TM + i;
        if (gr >= n) continue;
#pragma unroll
        for (int j = 0; j < TN; j += 4) {
            int gc = colBase + tx * TN + j;
            float4 o;
            o.x = acc[i][j + 0] + __ldg(bias + gc + 0);
            o.y = acc[i][j + 1] + __ldg(bias + gc + 1);
            o.z = acc[i][j + 2] + __ldg(bias + gc + 2);
            o.w = acc[i][j + 3] + __ldg(bias + gc + 3);
            if (RELU) {
                o.x = fmaxf(o.x, 0.f); o.y = fmaxf(o.y, 0.f);
                o.z = fmaxf(o.z, 0.f); o.w = fmaxf(o.w, 0.f);
            }
            *(float4*)(C + (size_t)gr * Fout + gc) = o;
        }
    }
}

// ---------------------------------------------------------------------------
extern "C" void kernel_launch(void* const* d_in, const int* in_sizes, int n_in,
                              void* d_out, int out_size) {
    const float* x    = (const float*)d_in[0];
    const int*   row  = (const int*)  d_in[1];
    const int*   col  = (const int*)  d_in[2];
    const float* vals = (const float*)d_in[3];
    const float* eps0 = (const float*)d_in[4];
    const float* W1a  = (const float*)d_in[5];
    const float* b1a  = (const float*)d_in[6];
    const float* W2a  = (const float*)d_in[7];
    const float* b2a  = (const float*)d_in[8];
    const float* eps1 = (const float*)d_in[9];
    const float* W1b  = (const float*)d_in[10];
    const float* b1b  = (const float*)d_in[11];
    const float* W2b  = (const float*)d_in[12];
    const float* b2b  = (const float*)d_in[13];
    const float* Wf1  = (const float*)d_in[14];
    const float* bf1  = (const float*)d_in[15];
    const float* Wf2  = (const float*)d_in[16];
    const float* bf2  = (const float*)d_in[17];
    float* out = (float*)d_out;

    const int n = NN;
    const int E = in_sizes[1];

    float *bufA, *bufB, *bufC;
    cudaGetSymbolAddress((void**)&bufA, g_bufA);
    cudaGetSymbolAddress((void**)&bufB, g_bufB);
    cudaGetSymbolAddress((void**)&bufC, g_bufC);

    const int mblocks = (n + 127) / 128;
    dim3 g256(mblocks, 2);   // Fout=256, BN=128
    dim3 g64(mblocks, 1);    // Fout=64,  BN=64
    const int spmm_blocks = (E + 7) / 8;  // 8 warps per 256-thread block

    // ---- GIN layer 1 (D=128 in) ----
    {
        int n4 = n * 128 / 4;
        scale_init_kernel<<<(n4 + 255) / 256, 256>>>(bufA, x, eps0, n4);
        spmm_kernel<128><<<spmm_blocks, 256>>>(row, col, vals, x, bufA, E);
        gemm_bias_kernel<128, true ><<<g256, 256>>>(bufA, W1a, b1a, bufB, n, 128, 256);
        gemm_bias_kernel<128, false><<<g256, 256>>>(bufB, W2a, b2a, bufC, n, 256, 256);
    }
    // ---- GIN layer 2 (D=256 in) ----
    {
        int n4 = n * 256 / 4;
        scale_init_kernel<<<(n4 + 255) / 256, 256>>>(bufA, bufC, eps1, n4);
        spmm_kernel<256><<<spmm_blocks, 256>>>(row, col, vals, bufC, bufA, E);
        gemm_bias_kernel<128, true ><<<g256, 256>>>(bufA, W1b, b1b, bufB, n, 256, 256);
        gemm_bias_kernel<128, false><<<g256, 256>>>(bufB, W2b, b2b, bufC, n, 256, 256);
    }
    // ---- Final MLP ----
    gemm_bias_kernel<128, true ><<<g256, 256>>>(bufC, Wf1, bf1, bufB, n, 256, 256);
    gemm_bias_kernel<64,  false><<<g64, 128>>>(bufB, Wf2, bf2, out, n, 256, 64);
}

// round 2
// speedup vs baseline: 3.0783x; 3.0783x over previous
#include <cuda_runtime.h>
#include <cstdint>

// GIN: h = GINConv(x) -> GINConv(h) -> relu(Wf1) -> Wf2
// N=100000, E=1600000, D_IN=128, D_H=256, D_OUT=64

static constexpr int NN = 100000;
static constexpr int DHMAX = 256;

// Scratch ping-pong buffers (no cudaMalloc allowed)
__device__ __align__(128) float g_bufA[(size_t)NN * DHMAX];
__device__ __align__(128) float g_bufB[(size_t)NN * DHMAX];
__device__ __align__(128) float g_bufC[(size_t)NN * DHMAX];

// ---------------------------------------------------------------------------
// h[i] = (1 + eps) * x[i]   (seed the accumulator before edge scatter-adds)
// ---------------------------------------------------------------------------
__global__ void scale_init_kernel(float* __restrict__ h, const float* __restrict__ x,
                                  const float* __restrict__ eps, int n4) {
    float s = 1.0f + eps[0];
    const float4* x4 = (const float4*)x;
    float4* h4 = (float4*)h;
    for (int i = blockIdx.x * blockDim.x + threadIdx.x; i < n4;
         i += gridDim.x * blockDim.x) {
        float4 v = x4[i];
        h4[i] = make_float4(s * v.x, s * v.y, s * v.z, s * v.w);
    }
}

// Vectorized no-return global reduction (REDG)
__device__ __forceinline__ void red_add_v4(float* p, float a, float b, float c, float d) {
    asm volatile("red.global.add.v4.f32 [%0], {%1,%2,%3,%4};"
                 :: "l"(p), "f"(a), "f"(b), "f"(c), "f"(d)
                 : "memory");
}

// ---------------------------------------------------------------------------
// SpMM scatter: h[row[e]] += vals[e] * x[col[e]]   (one warp per edge)
// ---------------------------------------------------------------------------
template<int D>
__global__ void spmm_kernel(const int* __restrict__ row, const int* __restrict__ col,
                            const float* __restrict__ vals, const float* __restrict__ x,
                            float* __restrict__ h, int E) {
    int warp = (blockIdx.x * blockDim.x + threadIdx.x) >> 5;
    int lane = threadIdx.x & 31;
    if (warp >= E) return;
    int r = __ldg(row + warp);
    int c = __ldg(col + warp);
    float v = __ldg(vals + warp);
    const float4* xs = (const float4*)(x + (size_t)c * D);
    float* hd = h + (size_t)r * D;
#pragma unroll
    for (int i = 0; i < D / 128; i++) {
        int j = lane + i * 32;
        float4 xv = __ldg(xs + j);
        red_add_v4(hd + 4 * j, v * xv.x, v * xv.y, v * xv.z, v * xv.w);
    }
}

// ---------------------------------------------------------------------------
// TF32 tensor-core GEMM: C[n, Fout] = A[n, K] @ W[Fout, K]^T + bias (opt ReLU)
// BM=128, BN=(128|64), BK=32.  8 warps: 4 (M) x 2 (N); warp tile 32 x BN/2.
// mma.sync.m16n8k8.tf32, ldmatrix feeds, RNA conversion on the STS path.
// ---------------------------------------------------------------------------
__device__ __forceinline__ uint32_t f2tf32(float f) {
    uint32_t r;
    asm("cvt.rna.tf32.f32 %0, %1;" : "=r"(r) : "f"(f));
    return r;
}

#define MMA_TF32(d, a, b0, b1)                                                     \
    asm volatile(                                                                  \
        "mma.sync.aligned.m16n8k8.row.col.f32.tf32.tf32.f32 "                      \
        "{%0,%1,%2,%3},{%4,%5,%6,%7},{%8,%9},{%0,%1,%2,%3};"                       \
        : "+f"((d)[0]), "+f"((d)[1]), "+f"((d)[2]), "+f"((d)[3])                   \
        : "r"((a)[0]), "r"((a)[1]), "r"((a)[2]), "r"((a)[3]), "r"(b0), "r"(b1))

#define LDSM_X4(r, addr)                                                           \
    asm volatile("ldmatrix.sync.aligned.m8n8.x4.shared.b16 {%0,%1,%2,%3},[%4];"    \
                 : "=r"((r)[0]), "=r"((r)[1]), "=r"((r)[2]), "=r"((r)[3])          \
                 : "r"(addr))

template<int BN, bool RELU>
__global__ __launch_bounds__(256)
void gemm_tf32_kernel(const float* __restrict__ A, const float* __restrict__ W,
                      const float* __restrict__ bias, float* __restrict__ C,
                      int n, int K, int Fout) {
    constexpr int BM = 128, BK = 32, PAD = BK + 4;   // 144B row stride
    constexpr int WN = BN / 2;                       // warp N tile
    constexpr int NB = WN / 8;                       // n8 tiles per warp
    constexpr int NB16 = WN / 16;                    // ldsm.x4 groups per warp (B)
    constexpr int AL4 = BM * (BK / 4) / 256;         // 4 float4/thread for A
    constexpr int BL4 = BN * (BK / 4) / 256;         // 4 or 2 for B

    __shared__ uint32_t As[BM * PAD];
    __shared__ uint32_t Bs[BN * PAD];

    const int tid = threadIdx.x;
    const int lane = tid & 31;
    const int wid = tid >> 5;
    const int wm = (wid & 3) * 32;       // warp M offset
    const int bn = (wid >> 2) * WN;      // warp N offset
    const int rowBase = blockIdx.x * BM;
    const int colBase = blockIdx.y * BN;

    float4 ra[AL4], rb[BL4];

    auto ldAB = [&](int k0) {
#pragma unroll
        for (int l = 0; l < AL4; l++) {
            int idx = tid + l * 256;
            int r = idx >> 3, c = (idx & 7) * 4;
            int gr = rowBase + r;
            ra[l] = (gr < n) ? *(const float4*)(A + (size_t)gr * K + k0 + c)
                             : make_float4(0.f, 0.f, 0.f, 0.f);
        }
#pragma unroll
        for (int l = 0; l < BL4; l++) {
            int idx = tid + l * 256;
            int r = idx >> 3, c = (idx & 7) * 4;
            rb[l] = *(const float4*)(W + (size_t)(colBase + r) * K + k0 + c);
        }
    };
    auto stAB = [&]() {
#pragma unroll
        for (int l = 0; l < AL4; l++) {
            int idx = tid + l * 256;
            int r = idx >> 3, c = (idx & 7) * 4;
            uint4 q;
            q.x = f2tf32(ra[l].x); q.y = f2tf32(ra[l].y);
            q.z = f2tf32(ra[l].z); q.w = f2tf32(ra[l].w);
            *(uint4*)&As[r * PAD + c] = q;
        }
#pragma unroll
        for (int l = 0; l < BL4; l++) {
            int idx = tid + l * 256;
            int r = idx >> 3, c = (idx & 7) * 4;
            uint4 q;
            q.x = f2tf32(rb[l].x); q.y = f2tf32(rb[l].y);
            q.z = f2tf32(rb[l].z); q.w = f2tf32(rb[l].w);
            *(uint4*)&Bs[r * PAD + c] = q;
        }
    };

    // ldmatrix per-thread source addresses
    // A: threads 0-15 -> rows 0-15 byte-col 0; threads 16-31 -> rows 0-15 byte-col 16
    const uint32_t aBase = (uint32_t)__cvta_generic_to_shared(
        &As[(wm + (lane & 15)) * PAD + (lane >> 4) * 4]);
    // B: t0-7 rows0-7 c0 | t8-15 rows0-7 c16 | t16-23 rows8-15 c0 | t24-31 rows8-15 c16
    const uint32_t bBase = (uint32_t)__cvta_generic_to_shared(
        &Bs[(bn + (((lane >> 4) << 3) | (lane & 7))) * PAD + (((lane >> 3) & 1) * 4)]);

    float acc[2][NB][4];
#pragma unroll
    for (int i = 0; i < 2; i++)
#pragma unroll
        for (int j = 0; j < NB; j++)
#pragma unroll
            for (int k = 0; k < 4; k++) acc[i][j][k] = 0.f;

    const int nk = K / BK;
    ldAB(0);
    stAB();
    __syncthreads();

    for (int kt = 0; kt < nk; kt++) {
        if (kt + 1 < nk) ldAB((kt + 1) * BK);   // prefetch next tile to regs

#pragma unroll
        for (int kk = 0; kk < 4; kk++) {
            uint32_t afr[2][4];
#pragma unroll
            for (int tm = 0; tm < 2; tm++)
                LDSM_X4(afr[tm], aBase + (uint32_t)(tm * 16 * PAD + kk * 8) * 4);
            uint32_t bfr[NB16][4];
#pragma unroll
            for (int j = 0; j < NB16; j++)
                LDSM_X4(bfr[j], bBase + (uint32_t)(j * 16 * PAD + kk * 8) * 4);
#pragma unroll
            for (int tm = 0; tm < 2; tm++)
#pragma unroll
                for (int j = 0; j < NB16; j++) {
                    MMA_TF32(acc[tm][2 * j + 0], afr[tm], bfr[j][0], bfr[j][1]);
                    MMA_TF32(acc[tm][2 * j + 1], afr[tm], bfr[j][2], bfr[j][3]);
                }
        }
        __syncthreads();
        if (kt + 1 < nk) {
            stAB();
            __syncthreads();
        }
    }

    // Epilogue: c0,c1 -> (row=lane/4, col=2*(lane%4)+{0,1}); c2,c3 -> row+8
#pragma unroll
    for (int tm = 0; tm < 2; tm++) {
#pragma unroll
        for (int half = 0; half < 2; half++) {
            int gr = rowBase + wm + tm * 16 + (lane >> 2) + half * 8;
            if (gr >= n) continue;
#pragma unroll
            for (int nt = 0; nt < NB; nt++) {
                int gc = colBase + bn + nt * 8 + 2 * (lane & 3);
                float2 bv = *(const float2*)(bias + gc);
                float o0 = acc[tm][nt][half * 2 + 0] + bv.x;
                float o1 = acc[tm][nt][half * 2 + 1] + bv.y;
                if (RELU) { o0 = fmaxf(o0, 0.f); o1 = fmaxf(o1, 0.f); }
                *(float2*)(C + (size_t)gr * Fout + gc) = make_float2(o0, o1);
            }
        }
    }
}

// ---------------------------------------------------------------------------
extern "C" void kernel_launch(void* const* d_in, const int* in_sizes, int n_in,
                              void* d_out, int out_size) {
    const float* x    = (const float*)d_in[0];
    const int*   row  = (const int*)  d_in[1];
    const int*   col  = (const int*)  d_in[2];
    const float* vals = (const float*)d_in[3];
    const float* eps0 = (const float*)d_in[4];
    const float* W1a  = (const float*)d_in[5];
    const float* b1a  = (const float*)d_in[6];
    const float* W2a  = (const float*)d_in[7];
    const float* b2a  = (const float*)d_in[8];
    const float* eps1 = (const float*)d_in[9];
    const float* W1b  = (const float*)d_in[10];
    const float* b1b  = (const float*)d_in[11];
    const float* W2b  = (const float*)d_in[12];
    const float* b2b  = (const float*)d_in[13];
    const float* Wf1  = (const float*)d_in[14];
    const float* bf1  = (const float*)d_in[15];
    const float* Wf2  = (const float*)d_in[16];
    const float* bf2  = (const float*)d_in[17];
    float* out = (float*)d_out;

    const int n = NN;
    const int E = in_sizes[1];

    float *bufA, *bufB, *bufC;
    cudaGetSymbolAddress((void**)&bufA, g_bufA);
    cudaGetSymbolAddress((void**)&bufB, g_bufB);
    cudaGetSymbolAddress((void**)&bufC, g_bufC);

    const int mblocks = (n + 127) / 128;
    dim3 g256(mblocks, 2);   // Fout=256, BN=128
    dim3 g64(mblocks, 1);    // Fout=64,  BN=64
    const int spmm_blocks = (E + 7) / 8;  // 8 warps per 256-thread block

    // ---- GIN layer 1 (D=128 in) ----
    {
        int n4 = n * 128 / 4;
        scale_init_kernel<<<(n4 + 255) / 256, 256>>>(bufA, x, eps0, n4);
        spmm_kernel<128><<<spmm_blocks, 256>>>(row, col, vals, x, bufA, E);
        gemm_tf32_kernel<128, true ><<<g256, 256>>>(bufA, W1a, b1a, bufB, n, 128, 256);
        gemm_tf32_kernel<128, false><<<g256, 256>>>(bufB, W2a, b2a, bufC, n, 256, 256);
    }
    // ---- GIN layer 2 (D=256 in) ----
    {
        int n4 = n * 256 / 4;
        scale_init_kernel<<<(n4 + 255) / 256, 256>>>(bufA, bufC, eps1, n4);
        spmm_kernel<256><<<spmm_blocks, 256>>>(row, col, vals, bufC, bufA, E);
        gemm_tf32_kernel<128, true ><<<g256, 256>>>(bufA, W1b, b1b, bufB, n, 256, 256);
        gemm_tf32_kernel<128, false><<<g256, 256>>>(bufB, W2b, b2b, bufC, n, 256, 256);
    }
    // ---- Final MLP ----
    gemm_tf32_kernel<128, true ><<<g256, 256>>>(bufC, Wf1, bf1, bufB, n, 256, 256);
    gemm_tf32_kernel<64,  false><<<g64, 256>>>(bufB, Wf2, bf2, out, n, 256, 64);
}

// round 3
// speedup vs baseline: 4.7365x; 1.5387x over previous
#include <cuda_runtime.h>
#include <cstdint>

// GIN: h = GINConv(x) -> GINConv(h) -> relu(Wf1) -> Wf2
// N=100000, E=1600000, D_IN=128, D_H=256, D_OUT=64

static constexpr int NN = 100000;
static constexpr int DHMAX = 256;
static constexpr int EMAX = 1700000;
static constexpr int SCAN_BLK = 1024;                      // elems per scan block
static constexpr int NSCAN = (NN + SCAN_BLK - 1) / SCAN_BLK;  // 98

// Scratch (no cudaMalloc allowed)
__device__ __align__(128) float g_bufA[(size_t)NN * DHMAX];
__device__ __align__(128) float g_bufB[(size_t)NN * DHMAX];
__device__ __align__(128) float g_bufC[(size_t)NN * DHMAX];
__device__ __align__(128) int2  g_csr_ev[EMAX];   // {col, val_bits}
__device__ int g_deg[NN];
__device__ int g_incl[NN];
__device__ int g_rowptr[NN];
__device__ int g_cursor[NN];
__device__ int g_bsum[NSCAN];
__device__ int g_boff[NSCAN];

// ---------------------------------------------------------------------------
// CSR build
// ---------------------------------------------------------------------------
__global__ void zero_deg_kernel(int* __restrict__ deg, int n) {
    int i = blockIdx.x * blockDim.x + threadIdx.x;
    if (i < n) deg[i] = 0;
}

__global__ void hist_kernel(const int* __restrict__ row, int* __restrict__ deg, int E) {
    int e = blockIdx.x * blockDim.x + threadIdx.x;
    if (e < E) atomicAdd(&deg[row[e]], 1);
}

// inclusive scan within 1024-elem blocks (256 thr x 4), block sums out
__global__ void scan1_kernel(const int* __restrict__ deg, int* __restrict__ incl,
                             int* __restrict__ bsum, int n) {
    __shared__ int s[256];
    int t = threadIdx.x;
    int base = blockIdx.x * SCAN_BLK + t * 4;
    int v0 = (base + 0 < n) ? deg[base + 0] : 0;
    int v1 = (base + 1 < n) ? deg[base + 1] : 0;
    int v2 = (base + 2 < n) ? deg[base + 2] : 0;
    int v3 = (base + 3 < n) ? deg[base + 3] : 0;
    int tsum = v0 + v1 + v2 + v3;
    s[t] = tsum;
    __syncthreads();
    for (int off = 1; off < 256; off <<= 1) {
        int add = (t >= off) ? s[t - off] : 0;
        __syncthreads();
        s[t] += add;
        __syncthreads();
    }
    int excl = s[t] - tsum;
    if (base + 0 < n) incl[base + 0] = excl + v0;
    if (base + 1 < n) incl[base + 1] = excl + v0 + v1;
    if (base + 2 < n) incl[base + 2] = excl + v0 + v1 + v2;
    if (base + 3 < n) incl[base + 3] = excl + tsum;
    if (t == 255) bsum[blockIdx.x] = s[255];
}

__global__ void scan2_kernel(const int* __restrict__ bsum, int* __restrict__ boff, int nb) {
    if (threadIdx.x == 0) {
        int run = 0;
        for (int i = 0; i < nb; i++) { boff[i] = run; run += bsum[i]; }
    }
}

__global__ void scan3_kernel(const int* __restrict__ incl, const int* __restrict__ deg,
                             const int* __restrict__ boff, int* __restrict__ rowptr,
                             int* __restrict__ cursor, int n) {
    int i = blockIdx.x * blockDim.x + threadIdx.x;
    if (i < n) {
        int start = incl[i] - deg[i] + boff[i / SCAN_BLK];
        rowptr[i] = start;
        cursor[i] = start;
    }
}

__global__ void fill_kernel(const int* __restrict__ row, const int* __restrict__ col,
                            const float* __restrict__ vals, int* __restrict__ cursor,
                            int2* __restrict__ ev, int E) {
    int e = blockIdx.x * blockDim.x + threadIdx.x;
    if (e < E) {
        int pos = atomicAdd(&cursor[row[e]], 1);
        ev[pos] = make_int2(col[e], __float_as_int(vals[e]));
    }
}

// ---------------------------------------------------------------------------
// CSR SpMM with fused eps-residual: h[i] = (1+eps)*x[i] + sum_e val*x[col]
// One warp per node; lane covers D/32 float4 chunks in registers.
// ---------------------------------------------------------------------------
template<int D>
__global__ __launch_bounds__(256)
void spmm_csr_kernel(const int* __restrict__ rowptr, const int* __restrict__ deg,
                     const int2* __restrict__ ev, const float* __restrict__ x,
                     const float* __restrict__ eps, float* __restrict__ h, int n) {
    constexpr int NC = D / 128;  // float4 chunks per lane
    int warp = (blockIdx.x * blockDim.x + threadIdx.x) >> 5;
    int lane = threadIdx.x & 31;
    if (warp >= n) return;

    float s = 1.0f + eps[0];
    const float4* xself = (const float4*)(x + (size_t)warp * D);
    float4 acc[NC];
#pragma unroll
    for (int i = 0; i < NC; i++) {
        float4 v = __ldg(xself + lane + 32 * i);
        acc[i] = make_float4(s * v.x, s * v.y, s * v.z, s * v.w);
    }

    int start = rowptr[warp];
    int len = deg[warp];
    for (int e = 0; e < len; e++) {
        int2 edge = __ldg(ev + start + e);       // broadcast
        float v = __int_as_float(edge.y);
        const float4* xs = (const float4*)(x + (size_t)edge.x * D);
#pragma unroll
        for (int i = 0; i < NC; i++) {
            float4 xv = __ldg(xs + lane + 32 * i);
            acc[i].x = fmaf(v, xv.x, acc[i].x);
            acc[i].y = fmaf(v, xv.y, acc[i].y);
            acc[i].z = fmaf(v, xv.z, acc[i].z);
            acc[i].w = fmaf(v, xv.w, acc[i].w);
        }
    }

    float4* hd = (float4*)(h + (size_t)warp * D);
#pragma unroll
    for (int i = 0; i < NC; i++) hd[lane + 32 * i] = acc[i];
}

// ---------------------------------------------------------------------------
// TF32 tensor-core GEMM: C[n, Fout] = A[n, K] @ W[Fout, K]^T + bias (opt ReLU)
// ---------------------------------------------------------------------------
__device__ __forceinline__ uint32_t f2tf32(float f) {
    uint32_t r;
    asm("cvt.rna.tf32.f32 %0, %1;" : "=r"(r) : "f"(f));
    return r;
}

#define MMA_TF32(d, a, b0, b1)                                                     \
    asm volatile(                                                                  \
        "mma.sync.aligned.m16n8k8.row.col.f32.tf32.tf32.f32 "                      \
        "{%0,%1,%2,%3},{%4,%5,%6,%7},{%8,%9},{%0,%1,%2,%3};"                       \
        : "+f"((d)[0]), "+f"((d)[1]), "+f"((d)[2]), "+f"((d)[3])                   \
        : "r"((a)[0]), "r"((a)[1]), "r"((a)[2]), "r"((a)[3]), "r"(b0), "r"(b1))

#define LDSM_X4(r, addr)                                                           \
    asm volatile("ldmatrix.sync.aligned.m8n8.x4.shared.b16 {%0,%1,%2,%3},[%4];"    \
                 : "=r"((r)[0]), "=r"((r)[1]), "=r"((r)[2]), "=r"((r)[3])          \
                 : "r"(addr))

template<int BN, bool RELU>
__global__ __launch_bounds__(256)
void gemm_tf32_kernel(const float* __restrict__ A, const float* __restrict__ W,
                      const float* __restrict__ bias, float* __restrict__ C,
                      int n, int K, int Fout) {
    constexpr int BM = 128, BK = 32, PAD = BK + 4;   // 144B row stride
    constexpr int WN = BN / 2;
    constexpr int NB = WN / 8;
    constexpr int NB16 = WN / 16;
    constexpr int AL4 = BM * (BK / 4) / 256;
    constexpr int BL4 = BN * (BK / 4) / 256;

    __shared__ uint32_t As[BM * PAD];
    __shared__ uint32_t Bs[BN * PAD];

    const int tid = threadIdx.x;
    const int lane = tid & 31;
    const int wid = tid >> 5;
    const int wm = (wid & 3) * 32;
    const int bn = (wid >> 2) * WN;
    const int rowBase = blockIdx.x * BM;
    const int colBase = blockIdx.y * BN;

    float4 ra[AL4], rb[BL4];

    auto ldAB = [&](int k0) {
#pragma unroll
        for (int l = 0; l < AL4; l++) {
            int idx = tid + l * 256;
            int r = idx >> 3, c = (idx & 7) * 4;
            int gr = rowBase + r;
            ra[l] = (gr < n) ? *(const float4*)(A + (size_t)gr * K + k0 + c)
                             : make_float4(0.f, 0.f, 0.f, 0.f);
        }
#pragma unroll
        for (int l = 0; l < BL4; l++) {
            int idx = tid + l * 256;
            int r = idx >> 3, c = (idx & 7) * 4;
            rb[l] = *(const float4*)(W + (size_t)(colBase + r) * K + k0 + c);
        }
    };
    auto stAB = [&]() {
#pragma unroll
        for (int l = 0; l < AL4; l++) {
            int idx = tid + l * 256;
            int r = idx >> 3, c = (idx & 7) * 4;
            uint4 q;
            q.x = f2tf32(ra[l].x); q.y = f2tf32(ra[l].y);
            q.z = f2tf32(ra[l].z); q.w = f2tf32(ra[l].w);
            *(uint4*)&As[r * PAD + c] = q;
        }
#pragma unroll
        for (int l = 0; l < BL4; l++) {
            int idx = tid + l * 256;
            int r = idx >> 3, c = (idx & 7) * 4;
            uint4 q;
            q.x = f2tf32(rb[l].x); q.y = f2tf32(rb[l].y);
            q.z = f2tf32(rb[l].z); q.w = f2tf32(rb[l].w);
            *(uint4*)&Bs[r * PAD + c] = q;
        }
    };

    const uint32_t aBase = (uint32_t)__cvta_generic_to_shared(
        &As[(wm + (lane & 15)) * PAD + (lane >> 4) * 4]);
    const uint32_t bBase = (uint32_t)__cvta_generic_to_shared(
        &Bs[(bn + (((lane >> 4) << 3) | (lane & 7))) * PAD + (((lane >> 3) & 1) * 4)]);

    float acc[2][NB][4];
#pragma unroll
    for (int i = 0; i < 2; i++)
#pragma unroll
        for (int j = 0; j < NB; j++)
#pragma unroll
            for (int k = 0; k < 4; k++) acc[i][j][k] = 0.f;

    const int nk = K / BK;
    ldAB(0);
    stAB();
    __syncthreads();

    for (int kt = 0; kt < nk; kt++) {
        if (kt + 1 < nk) ldAB((kt + 1) * BK);

#pragma unroll
        for (int kk = 0; kk < 4; kk++) {
            uint32_t afr[2][4];
#pragma unroll
            for (int tm = 0; tm < 2; tm++)
                LDSM_X4(afr[tm], aBase + (uint32_t)(tm * 16 * PAD + kk * 8) * 4);
            uint32_t bfr[NB16][4];
#pragma unroll
            for (int j = 0; j < NB16; j++)
                LDSM_X4(bfr[j], bBase + (uint32_t)(j * 16 * PAD + kk * 8) * 4);
#pragma unroll
            for (int tm = 0; tm < 2; tm++)
#pragma unroll
                for (int j = 0; j < NB16; j++) {
                    MMA_TF32(acc[tm][2 * j + 0], afr[tm], bfr[j][0], bfr[j][1]);
                    MMA_TF32(acc[tm][2 * j + 1], afr[tm], bfr[j][2], bfr[j][3]);
                }
        }
        __syncthreads();
        if (kt + 1 < nk) {
            stAB();
            __syncthreads();
        }
    }

#pragma unroll
    for (int tm = 0; tm < 2; tm++) {
#pragma unroll
        for (int half = 0; half < 2; half++) {
            int gr = rowBase + wm + tm * 16 + (lane >> 2) + half * 8;
            if (gr >= n) continue;
#pragma unroll
            for (int nt = 0; nt < NB; nt++) {
                int gc = colBase + bn + nt * 8 + 2 * (lane & 3);
                float2 bv = *(const float2*)(bias + gc);
                float o0 = acc[tm][nt][half * 2 + 0] + bv.x;
                float o1 = acc[tm][nt][half * 2 + 1] + bv.y;
                if (RELU) { o0 = fmaxf(o0, 0.f); o1 = fmaxf(o1, 0.f); }
                *(float2*)(C + (size_t)gr * Fout + gc) = make_float2(o0, o1);
            }
        }
    }
}

// ---------------------------------------------------------------------------
extern "C" void kernel_launch(void* const* d_in, const int* in_sizes, int n_in,
                              void* d_out, int out_size) {
    const float* x    = (const float*)d_in[0];
    const int*   row  = (const int*)  d_in[1];
    const int*   col  = (const int*)  d_in[2];
    const float* vals = (const float*)d_in[3];
    const float* eps0 = (const float*)d_in[4];
    const float* W1a  = (const float*)d_in[5];
    const float* b1a  = (const float*)d_in[6];
    const float* W2a  = (const float*)d_in[7];
    const float* b2a  = (const float*)d_in[8];
    const float* eps1 = (const float*)d_in[9];
    const float* W1b  = (const float*)d_in[10];
    const float* b1b  = (const float*)d_in[11];
    const float* W2b  = (const float*)d_in[12];
    const float* b2b  = (const float*)d_in[13];
    const float* Wf1  = (const float*)d_in[14];
    const float* bf1  = (const float*)d_in[15];
    const float* Wf2  = (const float*)d_in[16];
    const float* bf2  = (const float*)d_in[17];
    float* out = (float*)d_out;

    const int n = NN;
    const int E = in_sizes[1];

    float *bufA, *bufB, *bufC;
    int *deg, *incl, *rowptr, *cursor, *bsum, *boff;
    int2* ev;
    cudaGetSymbolAddress((void**)&bufA, g_bufA);
    cudaGetSymbolAddress((void**)&bufB, g_bufB);
    cudaGetSymbolAddress((void**)&bufC, g_bufC);
    cudaGetSymbolAddress((void**)&deg, g_deg);
    cudaGetSymbolAddress((void**)&incl, g_incl);
    cudaGetSymbolAddress((void**)&rowptr, g_rowptr);
    cudaGetSymbolAddress((void**)&cursor, g_cursor);
    cudaGetSymbolAddress((void**)&bsum, g_bsum);
    cudaGetSymbolAddress((void**)&boff, g_boff);
    cudaGetSymbolAddress((void**)&ev, g_csr_ev);

    const int mblocks = (n + 127) / 128;
    dim3 g256(mblocks, 2);   // Fout=256, BN=128
    dim3 g64(mblocks, 1);    // Fout=64,  BN=64
    const int spmm_blocks = (n + 7) / 8;  // 8 warps (nodes) per 256-thread block

    // ---- CSR build (shared by both GIN layers) ----
    zero_deg_kernel<<<(n + 255) / 256, 256>>>(deg, n);
    hist_kernel<<<(E + 255) / 256, 256>>>(row, deg, E);
    scan1_kernel<<<NSCAN, 256>>>(deg, incl, bsum, n);
    scan2_kernel<<<1, 32>>>(bsum, boff, NSCAN);
    scan3_kernel<<<(n + 255) / 256, 256>>>(incl, deg, boff, rowptr, cursor, n);
    fill_kernel<<<(E + 255) / 256, 256>>>(row, col, vals, cursor, ev, E);

    // ---- GIN layer 1 (D=128 in) ----
    spmm_csr_kernel<128><<<spmm_blocks, 256>>>(rowptr, deg, ev, x, eps0, bufA, n);
    gemm_tf32_kernel<128, true ><<<g256, 256>>>(bufA, W1a, b1a, bufB, n, 128, 256);
    gemm_tf32_kernel<128, false><<<g256, 256>>>(bufB, W2a, b2a, bufC, n, 256, 256);

    // ---- GIN layer 2 (D=256 in) ----
    spmm_csr_kernel<256><<<spmm_blocks, 256>>>(rowptr, deg, ev, bufC, eps1, bufA, n);
    gemm_tf32_kernel<128, true ><<<g256, 256>>>(bufA, W1b, b1b, bufB, n, 256, 256);
    gemm_tf32_kernel<128, false><<<g256, 256>>>(bufB, W2b, b2b, bufC, n, 256, 256);

    // ---- Final MLP ----
    gemm_tf32_kernel<128, true ><<<g256, 256>>>(bufC, Wf1, bf1, bufB, n, 256, 256);
    gemm_tf32_kernel<64,  false><<<g64, 256>>>(bufB, Wf2, bf2, out, n, 256, 64);
}